// round 2
// baseline (speedup 1.0000x reference)
#include <cuda_runtime.h>
#include <cstdint>

// Problem constants (fixed by setup_inputs)
#define BN 8
#define TN 1024
#define CN 2048
#define L_LUT 1025
#define BB_HI ((1 << 24) - 1)   // b_bits = 24
#define EF 14                   // e_frac
#define EF_HALF (1LL << (EF - 1))     // 8192
#define EF_MASK ((1LL << EF) - 1)     // 16383

// ---- round-to-nearest-even right shift by 14, sign-magnitude (matches ref) ----
__device__ __forceinline__ long long rshr_rne14(long long x) {
    long long s = x >> 63;                                     // 0 or -1
    unsigned long long ax = (unsigned long long)((x ^ s) - s); // |x|, <= 2^45
    unsigned long long q = ax >> EF;
    unsigned long long r = ax & (unsigned long long)EF_MASK;
    unsigned long long inc = (r > (unsigned long long)EF_HALF) |
                             ((r == (unsigned long long)EF_HALF) & (q & 1ull));
    q += inc;
    long long v = (long long)q;
    return (v ^ s) - s;
}

// non-negative operand version (bb >= 0, e >= 0)
__device__ __forceinline__ long long rshr_rne14_nn(unsigned long long ax) {
    unsigned long long q = ax >> EF;
    unsigned long long r = ax & (unsigned long long)EF_MASK;
    unsigned long long inc = (r > (unsigned long long)EF_HALF) |
                             ((r == (unsigned long long)EF_HALF) & (q & 1ull));
    return (long long)(q + inc);
}

// ---- round-to-nearest-even division, d >= 1 (matches ref div_rne) ----
__device__ __forceinline__ int div_rne32(int a, unsigned int d) {
    unsigned int s  = (unsigned int)(a >> 31);               // 0 or 0xFFFFFFFF
    unsigned int ua = ((unsigned int)a ^ s) - s;             // |a| (handles INT_MIN)
    unsigned int q  = ua / d;
    unsigned int r  = ua - q * d;
    unsigned int tr = r << 1;                                // r < d <= 2^24-1: no overflow
    q += (unsigned int)((tr > d) | ((tr == d) & (q & 1u)));
    return (int)((q ^ s) - s);
}

__device__ __forceinline__ int sat_i32(long long x) {
    x = (x > 2147483647LL) ? 2147483647LL : x;
    x = (x < -2147483648LL) ? -2147483648LL : x;
    return (int)x;
}

__global__ void __launch_bounds__(128, 1)
wkv_int_kernel(const int* __restrict__ w_i, const int* __restrict__ u_i,
               const int* __restrict__ k_i, const int* __restrict__ v_i,
               const int* __restrict__ lut_g, float* __restrict__ y_out)
{
    __shared__ int lut[L_LUT];
    for (int i = threadIdx.x; i < L_LUT; i += blockDim.x) lut[i] = lut_g[i];
    __syncthreads();

    const int gid = blockIdx.x * blockDim.x + threadIdx.x;   // 0 .. B*C-1
    const int b = gid >> 11;          // / CN
    const int c = gid & (CN - 1);

    const int w = w_i[c];
    const int u = u_i[c];

    const int base = (b * TN) * CN + c;                      // < 2^24, fits int
    const int* __restrict__ kp = k_i + base;
    const int* __restrict__ vp = v_i + base;
    float* __restrict__ yp = y_out + base;

    int pp = -(1 << 15);   // _qmin_signed(p_bits=16)
    int aa = 0;
    int bb = 0;

    // Prefetch pipeline: groups of 4 timesteps, one group ahead.
    int kc[4], vc[4];
#pragma unroll
    for (int j = 0; j < 4; j++) {
        kc[j] = kp[j * CN];
        vc[j] = vp[j * CN];
    }

    for (int t0 = 0; t0 < TN; t0 += 4) {
        // issue next group's loads early (clamped index on final group: harmless reload)
        const int tn = (t0 + 4 < TN) ? (t0 + 4) : (TN - 4);
        int kn[4], vn[4];
#pragma unroll
        for (int j = 0; j < 4; j++) {
            kn[j] = kp[(tn + j) * CN];
            vn[j] = vp[(tn + j) * CN];
        }

#pragma unroll
        for (int j = 0; j < 4; j++) {
            const int kk = kc[j];
            const int vv = vc[j];

            // ---- output half-step (bonus u) ----
            const int ww = kk + u;
            const int p  = (pp > ww) ? pp : ww;
            int i1 = pp - p + 1024; i1 = (i1 > 0) ? i1 : 0;  // step_i=1 -> idx = clip(d+1024,0,1024); d<=0
            int i2 = ww - p + 1024; i2 = (i2 > 0) ? i2 : 0;
            const long long e1 = (long long)lut[i1];
            const long long e2 = (long long)lut[i2];

            long long a1 = rshr_rne14((long long)aa * e1) + (long long)vv * e2;
            const int aa1 = sat_i32(a1);
            long long b1 = rshr_rne14_nn((unsigned long long)((long long)bb * e1)) + e2;
            const int bb1 = (b1 > (long long)BB_HI) ? BB_HI : (int)b1;   // b1 >= 0 always

            const unsigned int den = (unsigned int)((bb1 > 1) ? bb1 : 1);
            const int y = div_rne32(aa1, den);
            yp[(t0 + j) * CN] = (float)y;   // output buffer is float32 per metadata

            // ---- state half-step (decay w) ----
            const int ww2 = pp + w;
            const int p2  = (ww2 > kk) ? ww2 : kk;
            int i1n = ww2 - p2 + 1024; i1n = (i1n > 0) ? i1n : 0;
            int i2n = kk  - p2 + 1024; i2n = (i2n > 0) ? i2n : 0;
            const long long e1n = (long long)lut[i1n];
            const long long e2n = (long long)lut[i2n];

            long long a2 = rshr_rne14((long long)aa1 * e1n) + (long long)vv * e2n;
            aa = sat_i32(a2);
            long long b2 = rshr_rne14_nn((unsigned long long)((long long)bb1 * e1n)) + e2n;
            bb = (b2 > (long long)BB_HI) ? BB_HI : (int)b2;
            pp = p2;
        }

#pragma unroll
        for (int j = 0; j < 4; j++) { kc[j] = kn[j]; vc[j] = vn[j]; }
    }
}

extern "C" void kernel_launch(void* const* d_in, const int* in_sizes, int n_in,
                              void* d_out, int out_size)
{
    (void)in_sizes; (void)n_in; (void)out_size;
    const int* w_i = (const int*)d_in[0];
    const int* u_i = (const int*)d_in[1];
    const int* k_i = (const int*)d_in[2];
    const int* v_i = (const int*)d_in[3];
    const int* lut = (const int*)d_in[4];
    float* y = (float*)d_out;

    // B*C = 16384 threads: 128 blocks x 128 threads -> ~1 warp per SMSP on 128 SMs
    wkv_int_kernel<<<128, 128>>>(w_i, u_i, k_i, v_i, lut, y);
}

// round 3
// speedup vs baseline: 1.3113x; 1.3113x over previous
#include <cuda_runtime.h>
#include <cstdint>

// Problem constants (fixed by setup_inputs)
#define TN 1024
#define CN 2048
#define L_LUT 1025
#define BB_HI 0x00FFFFFFu        // (1<<24)-1, b_bits = 24
#define EF 14                    // e_frac

// ---- RNE division, d >= 1 (matches ref div_rne); off the critical path ----
__device__ __forceinline__ int div_rne32(int a, unsigned int d) {
    unsigned int s  = (unsigned int)(a >> 31);               // 0 or 0xFFFFFFFF
    unsigned int ua = ((unsigned int)a ^ s) - s;             // |a| (handles INT_MIN)
    unsigned int q  = ua / d;
    unsigned int r  = ua - q * d;
    unsigned int tr = r << 1;                                // r < d <= 2^24-1: no overflow
    q += (unsigned int)((tr > d) | ((tr == d) & (q & 1u)));
    return (int)((q ^ s) - s);
}

// saturating int32 add: exactly clip(a+b, INT_MIN, INT_MAX) for exact int32 a,b
__device__ __forceinline__ int add_sat_s32(int a, int b) {
    int r;
    asm("add.sat.s32 %0, %1, %2;" : "=r"(r) : "r"(a), "r"(b));
    return r;
}

// RNE(aa * e / 2^14): result provably fits int32 (|aa|<=2^31, 0<=e<=2^14)
// identity: (x + 8191 + ((x>>14)&1)) >> 14  == round-to-nearest-even
__device__ __forceinline__ int rne_mulshift_s(int aa, int e) {
    long long prod = (long long)aa * (long long)e;           // IMAD.WIDE
    unsigned int lo = (unsigned int)prod;
    unsigned int bias = 8191u + ((lo >> EF) & 1u);
    prod += (long long)bias;                                 // IADD3 + IADD3.X
    return (int)(prod >> EF);                                // funnel shift, low word only
}

// RNE(bb * e / 2^14) for 0<=bb<2^24, 0<=e<=2^14 : pure unsigned, result < 2^24
__device__ __forceinline__ unsigned int rne_mulshift_u(unsigned int bb, unsigned int e) {
    unsigned long long prod = (unsigned long long)bb * e;    // IMAD.WIDE.U32
    unsigned int lo = (unsigned int)prod;
    unsigned int bias = 8191u + ((lo >> EF) & 1u);
    prod += bias;
    return (unsigned int)(prod >> EF);
}

__global__ void __launch_bounds__(128, 1)
wkv_int_kernel(const int* __restrict__ w_i, const int* __restrict__ u_i,
               const int* __restrict__ k_i, const int* __restrict__ v_i,
               const int* __restrict__ lut_g, float* __restrict__ y_out)
{
    __shared__ int lut[L_LUT];
    for (int i = threadIdx.x; i < L_LUT; i += blockDim.x) lut[i] = lut_g[i];
    __syncthreads();

    const int gid = blockIdx.x * blockDim.x + threadIdx.x;   // 0 .. B*C-1
    const int b = gid >> 11;
    const int c = gid & (CN - 1);

    const int w = w_i[c];
    const int u = u_i[c];

    const int base = (b * TN) * CN + c;                      // < 2^24
    const int* __restrict__ kp = k_i + base;
    const int* __restrict__ vp = v_i + base;
    float* __restrict__ yp = y_out + base;

    int pp = -(1 << 15);     // _qmin_signed(p_bits=16)
    int aa = 0;
    unsigned int bb = 0;

    // Prefetch pipeline: groups of 4 timesteps, one group ahead.
    int kc[4], vc[4];
#pragma unroll
    for (int j = 0; j < 4; j++) {
        kc[j] = kp[j * CN];
        vc[j] = vp[j * CN];
    }

    for (int t0 = 0; t0 < TN; t0 += 4) {
        const int tn = (t0 + 4 < TN) ? (t0 + 4) : (TN - 4);  // last group: harmless reload
        int kn[4], vn[4];
#pragma unroll
        for (int j = 0; j < 4; j++) {
            kn[j] = kp[(tn + j) * CN];
            vn[j] = vp[(tn + j) * CN];
        }

#pragma unroll
        for (int j = 0; j < 4; j++) {
            const int kk = kc[j];
            const int vv = vc[j];

            // ---- index chains for BOTH half-steps (short; lets LDS issue early) ----
            // output half (bonus u):
            const int ww = kk + u;
            const int p  = (pp > ww) ? pp : ww;
            int i1 = pp - p + 1024; i1 = (i1 > 0) ? i1 : 0;  // step_i=1, d<=0
            int i2 = ww - p + 1024; i2 = (i2 > 0) ? i2 : 0;
            // state half (decay w):
            const int ww2 = pp + w;
            const int p2  = (ww2 > kk) ? ww2 : kk;
            int i1n = ww2 - p2 + 1024; i1n = (i1n > 0) ? i1n : 0;
            int i2n = kk  - p2 + 1024; i2n = (i2n > 0) ? i2n : 0;

            const int e1  = lut[i1];
            const int e2  = lut[i2];
            const int e1n = lut[i1n];
            const int e2n = lut[i2n];
            pp = p2;

            // ---- output half-step ----
            const int aa1 = add_sat_s32(rne_mulshift_s(aa, e1), vv * e2);
            unsigned int b1 = rne_mulshift_u(bb, (unsigned int)e1) + (unsigned int)e2;
            const unsigned int bb1 = (b1 > BB_HI) ? BB_HI : b1;

            const unsigned int den = (bb1 > 1u) ? bb1 : 1u;
            const int y = div_rne32(aa1, den);
            yp[(t0 + j) * CN] = (float)y;

            // ---- state half-step ----
            aa = add_sat_s32(rne_mulshift_s(aa1, e1n), vv * e2n);
            unsigned int b2 = rne_mulshift_u(bb1, (unsigned int)e1n) + (unsigned int)e2n;
            bb = (b2 > BB_HI) ? BB_HI : b2;
        }

#pragma unroll
        for (int j = 0; j < 4; j++) { kc[j] = kn[j]; vc[j] = vn[j]; }
    }
}

extern "C" void kernel_launch(void* const* d_in, const int* in_sizes, int n_in,
                              void* d_out, int out_size)
{
    (void)in_sizes; (void)n_in; (void)out_size;
    const int* w_i = (const int*)d_in[0];
    const int* u_i = (const int*)d_in[1];
    const int* k_i = (const int*)d_in[2];
    const int* v_i = (const int*)d_in[3];
    const int* lut = (const int*)d_in[4];
    float* y = (float*)d_out;

    // B*C = 16384 threads: 128 blocks x 128 threads -> 1 warp per SMSP on 128 SMs
    wkv_int_kernel<<<128, 128>>>(w_i, u_i, k_i, v_i, lut, y);
}

// round 4
// speedup vs baseline: 2.1329x; 1.6266x over previous
#include <cuda_runtime.h>
#include <cstdint>

// Problem constants (fixed by setup_inputs)
#define TN 1024
#define CN 2048
#define L_LUT 1025
#define BB_HI 0x00FFFFFFu        // (1<<24)-1, b_bits = 24
#define EF 14                    // e_frac
#define NPF 4                    // prefetch depth in groups (group = 4 timesteps)

// ---- RNE division, d >= 1 (matches ref div_rne); off the critical path ----
__device__ __forceinline__ int div_rne32(int a, unsigned int d) {
    unsigned int s  = (unsigned int)(a >> 31);
    unsigned int ua = ((unsigned int)a ^ s) - s;             // |a| (handles INT_MIN)
    unsigned int q  = ua / d;
    unsigned int r  = ua - q * d;
    unsigned int tr = r << 1;                                // r < d <= 2^24-1: no overflow
    q += (unsigned int)((tr > d) | ((tr == d) & (q & 1u)));
    return (int)((q ^ s) - s);
}

// saturating int32 add == clip(a+b, INT_MIN, INT_MAX) for exact int32 a,b
__device__ __forceinline__ int add_sat_s32(int a, int b) {
    int r;
    asm("add.sat.s32 %0, %1, %2;" : "=r"(r) : "r"(a), "r"(b));
    return r;
}

// RNE(aa * e / 2^14): result provably fits int32 (|aa|<=2^31, 0<=e<=2^14)
// identity: (x + 8191 + ((x>>14)&1)) >> 14  == round-to-nearest-even
__device__ __forceinline__ int rne_mulshift_s(int aa, int e) {
    long long prod = (long long)aa * (long long)e;           // IMAD.WIDE
    unsigned int lo = (unsigned int)prod;
    unsigned int bias = 8191u + ((lo >> EF) & 1u);
    prod += (long long)bias;
    return (int)(prod >> EF);
}

// RNE(bb * e / 2^14) for 0<=bb<2^24, 0<=e<=2^14 : pure unsigned, result < 2^24
__device__ __forceinline__ unsigned int rne_mulshift_u(unsigned int bb, unsigned int e) {
    unsigned long long prod = (unsigned long long)bb * e;    // IMAD.WIDE.U32
    unsigned int lo = (unsigned int)prod;
    unsigned int bias = 8191u + ((lo >> EF) & 1u);
    prod += bias;
    return (unsigned int)(prod >> EF);
}

__global__ void __launch_bounds__(128, 1)
wkv_int_kernel(const int* __restrict__ w_i, const int* __restrict__ u_i,
               const int* __restrict__ k_i, const int* __restrict__ v_i,
               const int* __restrict__ lut_g, float* __restrict__ y_out)
{
    __shared__ int lut[L_LUT];
    for (int i = threadIdx.x; i < L_LUT; i += blockDim.x) lut[i] = lut_g[i];
    __syncthreads();

    const int gid = blockIdx.x * blockDim.x + threadIdx.x;   // 0 .. B*C-1
    const int b = gid >> 11;
    const int c = gid & (CN - 1);

    const int w = w_i[c];
    const int u = u_i[c];

    const int base = (b * TN) * CN + c;                      // < 2^24
    const int* __restrict__ kp = k_i + base;
    const int* __restrict__ vp = v_i + base;
    float* __restrict__ yp = y_out + base;

    int pp = -(1 << 15);     // _qmin_signed(p_bits=16)
    int aa = 0;
    unsigned int bb = 0;

    // Deep prefetch ring: NPF groups of 4 timesteps in flight (distance 16 steps)
    int kbuf[NPF][4], vbuf[NPF][4];
#pragma unroll
    for (int s = 0; s < NPF; s++) {
#pragma unroll
        for (int j = 0; j < 4; j++) {
            kbuf[s][j] = kp[(s * 4 + j) * CN];
            vbuf[s][j] = vp[(s * 4 + j) * CN];
        }
    }

    for (int t0 = 0; t0 < TN; t0 += 4 * NPF) {
#pragma unroll
        for (int s = 0; s < NPF; s++) {
            // consume this slot into temps
            int kc[4], vc[4];
#pragma unroll
            for (int j = 0; j < 4; j++) { kc[j] = kbuf[s][j]; vc[j] = vbuf[s][j]; }

            // refill slot with group NPF ahead (clamped tail: harmless reload)
            int tf = t0 + (s + NPF) * 4;
            if (tf > TN - 4) tf = TN - 4;
#pragma unroll
            for (int j = 0; j < 4; j++) {
                kbuf[s][j] = kp[(tf + j) * CN];
                vbuf[s][j] = vp[(tf + j) * CN];
            }

            const int tb = t0 + s * 4;
#pragma unroll
            for (int j = 0; j < 4; j++) {
                const int kk = kc[j];
                const int vv = vc[j];

                // ---- index chains for BOTH half-steps (short; LDS issues early) ----
                const int ww = kk + u;
                const int p  = (pp > ww) ? pp : ww;
                int i1 = pp - p + 1024; i1 = (i1 > 0) ? i1 : 0;  // step_i=1, d<=0
                int i2 = ww - p + 1024; i2 = (i2 > 0) ? i2 : 0;
                const int ww2 = pp + w;
                const int p2  = (ww2 > kk) ? ww2 : kk;
                int i1n = ww2 - p2 + 1024; i1n = (i1n > 0) ? i1n : 0;
                int i2n = kk  - p2 + 1024; i2n = (i2n > 0) ? i2n : 0;

                const int e1  = lut[i1];
                const int e2  = lut[i2];
                const int e1n = lut[i1n];
                const int e2n = lut[i2n];
                pp = p2;

                // ---- output half-step ----
                const int aa1 = add_sat_s32(rne_mulshift_s(aa, e1), vv * e2);
                unsigned int b1 = rne_mulshift_u(bb, (unsigned int)e1) + (unsigned int)e2;
                const unsigned int bb1 = (b1 > BB_HI) ? BB_HI : b1;

                const unsigned int den = (bb1 > 1u) ? bb1 : 1u;
                const int y = div_rne32(aa1, den);
                yp[(tb + j) * CN] = (float)y;

                // ---- state half-step ----
                aa = add_sat_s32(rne_mulshift_s(aa1, e1n), vv * e2n);
                unsigned int b2 = rne_mulshift_u(bb1, (unsigned int)e1n) + (unsigned int)e2n;
                bb = (b2 > BB_HI) ? BB_HI : b2;
            }
        }
    }
}

extern "C" void kernel_launch(void* const* d_in, const int* in_sizes, int n_in,
                              void* d_out, int out_size)
{
    (void)in_sizes; (void)n_in; (void)out_size;
    const int* w_i = (const int*)d_in[0];
    const int* u_i = (const int*)d_in[1];
    const int* k_i = (const int*)d_in[2];
    const int* v_i = (const int*)d_in[3];
    const int* lut = (const int*)d_in[4];
    float* y = (float*)d_out;

    // B*C = 16384 threads: 128 blocks x 128 threads -> 1 warp per SMSP on 128 SMs
    wkv_int_kernel<<<128, 128>>>(w_i, u_i, k_i, v_i, lut, y);
}